// round 7
// baseline (speedup 1.0000x reference)
#include <cuda_runtime.h>
#include <cuda_fp16.h>
#include <cstdint>
#include <cstddef>

#define IN_F   1024
#define OUT_F  1024
#define POP    64
#define MROWS  16384

#define BM 128
#define BN 256
#define BK 32
#define GEMM_THREADS 256
#define NCH (IN_F / BK)            // 32 k-chunks

// smem stage layout: fp16 rows of 32 elems + 8 pad = 80B stride (conflict-free ldmatrix)
#define A_OFF    0                 // 128 rows x 80B = 10240
#define B_OFF    10240             // 256 rows x 80B = 20480
#define STAGE_SZ 30720
#define NSTAGE   4
#define SMEM_TOTAL (NSTAGE * STAGE_SZ)   // 122880 B

// ---------------- scratch (device globals; allocation is forbidden) --------
__device__ __align__(16) __half g_x[(size_t)MROWS * IN_F];
__device__ __align__(16) __half g_w[(size_t)OUT_F * IN_F];
__device__ float g_beff[OUT_F];

// ---------------- PTX helpers (portable to plain sm_103 target) ------------
__device__ __forceinline__ uint32_t smem_u32(const void* p) {
    uint32_t a;
    asm("{ .reg .u64 t; cvta.to.shared.u64 t, %1; cvt.u32.u64 %0, t; }" : "=r"(a) : "l"(p));
    return a;
}
#define CP16(dst_u32, gptr) \
    asm volatile("cp.async.cg.shared.global [%0], [%1], 16;" :: "r"(dst_u32), "l"(gptr) : "memory")
#define CP_COMMIT() asm volatile("cp.async.commit_group;" ::: "memory")
#define CP_WAIT2()  asm volatile("cp.async.wait_group 2;" ::: "memory")
#define CP_WAIT1()  asm volatile("cp.async.wait_group 1;" ::: "memory")
#define CP_WAIT0()  asm volatile("cp.async.wait_group 0;" ::: "memory")

#define LDSM4(r0, r1, r2, r3, addr)                                              \
    asm volatile("ldmatrix.sync.aligned.m8n8.x4.shared.b16 {%0,%1,%2,%3}, [%4];" \
        : "=r"(r0), "=r"(r1), "=r"(r2), "=r"(r3) : "r"(addr))

__device__ __forceinline__ void mma16816(float* d, const uint32_t* a, const uint32_t* b) {
    asm volatile(
        "mma.sync.aligned.m16n8k16.row.col.f32.f16.f16.f32 "
        "{%0,%1,%2,%3}, {%4,%5,%6,%7}, {%8,%9}, {%0,%1,%2,%3};"
        : "+f"(d[0]), "+f"(d[1]), "+f"(d[2]), "+f"(d[3])
        : "r"(a[0]), "r"(a[1]), "r"(a[2]), "r"(a[3]), "r"(b[0]), "r"(b[1]));
}

// ---------------------------------------------------------------------------
// Prep 1: w_eff = weight + sum_i s_i*wp_i (fp32 math), emitted as fp16
// ---------------------------------------------------------------------------
__global__ void reduce_weight_kernel(const float* __restrict__ weight,
                                     const float* __restrict__ scale,
                                     const float* __restrict__ wp) {
    __shared__ float s_scale[POP];
    if (threadIdx.x < POP) s_scale[threadIdx.x] = scale[threadIdx.x];
    __syncthreads();

    size_t base = ((size_t)blockIdx.x * blockDim.x + threadIdx.x) * 4;
    float4 acc = *reinterpret_cast<const float4*>(weight + base);
#pragma unroll 8
    for (int i = 0; i < POP; i++) {
        const float s = s_scale[i];
        float4 p = *reinterpret_cast<const float4*>(wp + (size_t)i * (OUT_F * IN_F) + base);
        acc.x += s * p.x; acc.y += s * p.y; acc.z += s * p.z; acc.w += s * p.w;
    }
    __half h[4] = {__float2half_rn(acc.x), __float2half_rn(acc.y),
                   __float2half_rn(acc.z), __float2half_rn(acc.w)};
    *reinterpret_cast<uint2*>(g_w + base) = *reinterpret_cast<uint2*>(h);
}

// ---------------------------------------------------------------------------
// Prep 2: x -> fp16
// ---------------------------------------------------------------------------
__global__ void convert_x_kernel(const float* __restrict__ x) {
    size_t base = ((size_t)blockIdx.x * blockDim.x + threadIdx.x) * 8;
    float4 a = *reinterpret_cast<const float4*>(x + base);
    float4 b = *reinterpret_cast<const float4*>(x + base + 4);
    __half h[8] = {__float2half_rn(a.x), __float2half_rn(a.y),
                   __float2half_rn(a.z), __float2half_rn(a.w),
                   __float2half_rn(b.x), __float2half_rn(b.y),
                   __float2half_rn(b.z), __float2half_rn(b.w)};
    *reinterpret_cast<uint4*>(g_x + base) = *reinterpret_cast<uint4*>(h);
}

// ---------------------------------------------------------------------------
// Prep 3: bias
// ---------------------------------------------------------------------------
__global__ void reduce_bias_kernel(const float* __restrict__ bias,
                                   const float* __restrict__ scale,
                                   const float* __restrict__ bp) {
    int j = blockIdx.x * blockDim.x + threadIdx.x;
    if (j >= OUT_F) return;
    float acc = bias[j];
#pragma unroll 8
    for (int i = 0; i < POP; i++) acc += scale[i] * bp[i * OUT_F + j];
    g_beff[j] = acc;
}

// ---------------------------------------------------------------------------
// GEMM via mma.sync fp16 single-pass: out = x @ w_eff^T + b_eff (fp32 acc)
// CTA 128x256x32, 256 threads (8 warps, 2x4), warp tile 64x64
// (128B smem traffic per HMMA -> smem at ~59% when tensor at 100%),
// 4-stage cp.async pipeline.
// ---------------------------------------------------------------------------
__global__ __launch_bounds__(GEMM_THREADS, 1)
void gemm_mma_kernel(float* __restrict__ out) {
    extern __shared__ char smem[];
    const uint32_t sb = smem_u32(smem);
    const int tid  = threadIdx.x;
    const int wid  = tid >> 5;
    const int lane = tid & 31;
    const int wm   = wid & 1;          // 2 m-warps (64 rows each)
    const int wn   = wid >> 1;         // 4 n-warps (64 cols each)
    const int m0   = blockIdx.y * BM;
    const int n0   = blockIdx.x * BN;

    float acc[4][8][4];
#pragma unroll
    for (int a = 0; a < 4; a++)
#pragma unroll
        for (int b = 0; b < 8; b++)
#pragma unroll
            for (int c = 0; c < 4; c++) acc[a][b][c] = 0.0f;

    // ---- per-thread ldmatrix base offsets (fragment maps validated in R4)
    const int g = lane >> 3, r = lane & 7;
    const uint32_t a_row_off = (uint32_t)((wm * 64 + (g & 1) * 8 + r) * 80);
    const uint32_t a_k_off   = (uint32_t)((g >> 1) * 16);
    const uint32_t b_row_off = (uint32_t)((wn * 64 + (g >> 1) * 8 + r) * 80);
    const uint32_t b_k_off   = (uint32_t)((g & 1) * 16);

    // ---- stage loader: 6 cp.async x 16B per thread (A: 512 units, B: 1024)
    auto load_stage = [&](int s, int kt) {
        const uint32_t st = sb + s * STAGE_SZ;
        const int krow = kt * BK;
#pragma unroll
        for (int it = 0; it < 2; it++) {
            int u = tid + it * 256, row = u >> 2, kc = u & 3;
            CP16(st + A_OFF + (uint32_t)(row * 80 + kc * 16),
                 g_x + (size_t)(m0 + row) * IN_F + krow + kc * 8);
        }
#pragma unroll
        for (int it = 0; it < 4; it++) {
            int u = tid + it * 256, row = u >> 2, kc = u & 3;
            CP16(st + B_OFF + (uint32_t)(row * 80 + kc * 16),
                 g_w + (size_t)(n0 + row) * IN_F + krow + kc * 8);
        }
        CP_COMMIT();
    };

    // ---- pipeline prologue: 3 stages in flight
    load_stage(0, 0);
    load_stage(1, 1);
    load_stage(2, 2);

    for (int c = 0; c < NCH; c++) {
        if (c + 3 <= NCH)      { CP_WAIT2(); }
        else if (c + 2 <= NCH) { CP_WAIT1(); }
        else                   { CP_WAIT0(); }
        __syncthreads();                       // chunk c resident; stage (c+3)%4 free
        if (c + 3 < NCH) load_stage((c + 3) % NSTAGE, c + 3);

        const uint32_t st = sb + (c % NSTAGE) * STAGE_SZ;
#pragma unroll
        for (int ks = 0; ks < 2; ks++) {
            uint32_t ah[4][4];
#pragma unroll
            for (int mt = 0; mt < 4; mt++) {
                uint32_t aaddr = st + A_OFF + a_row_off + (uint32_t)(mt * 1280)
                               + a_k_off + (uint32_t)(ks * 32);
                LDSM4(ah[mt][0], ah[mt][1], ah[mt][2], ah[mt][3], aaddr);
            }
#pragma unroll
            for (int np = 0; np < 4; np++) {
                uint32_t bh[4];
                uint32_t baddr = st + B_OFF + b_row_off + (uint32_t)(np * 1280)
                               + b_k_off + (uint32_t)(ks * 32);
                LDSM4(bh[0], bh[1], bh[2], bh[3], baddr);
#pragma unroll
                for (int mt = 0; mt < 4; mt++) {
                    mma16816(acc[mt][2 * np],     ah[mt], bh);
                    mma16816(acc[mt][2 * np + 1], ah[mt], bh + 2);
                }
            }
        }
    }

    // ---- epilogue: c-frag m16n8 layout: rows lane/4 & +8, cols 2*(lane%4)
    const int erow = lane >> 2;
    const int ecol = 2 * (lane & 3);
#pragma unroll
    for (int mt = 0; mt < 4; mt++) {
        const int mrow = m0 + wm * 64 + mt * 16 + erow;
#pragma unroll
        for (int j = 0; j < 8; j++) {
            const int col = n0 + wn * 64 + j * 8 + ecol;
            const float b0 = g_beff[col], b1 = g_beff[col + 1];
            float2 v0 = make_float2(acc[mt][j][0] + b0, acc[mt][j][1] + b1);
            float2 v1 = make_float2(acc[mt][j][2] + b0, acc[mt][j][3] + b1);
            *reinterpret_cast<float2*>(out + (size_t)mrow * OUT_F + col)       = v0;
            *reinterpret_cast<float2*>(out + (size_t)(mrow + 8) * OUT_F + col) = v1;
        }
    }
}

// ---------------------------------------------------------------------------
// Launch. Inputs identified BY ELEMENT COUNT (all unique, order-independent).
// fp16 inputs arrive as fp32 on device (confirmed R3).
// ---------------------------------------------------------------------------
extern "C" void kernel_launch(void* const* d_in, const int* in_sizes, int n_in,
                              void* d_out, int out_size) {
    const float *x = nullptr, *weight = nullptr, *bias = nullptr,
                *scale = nullptr, *wp = nullptr, *bp = nullptr;
    for (int i = 0; i < n_in; i++) {
        switch (in_sizes[i]) {
            case 16777216: x      = (const float*)d_in[i]; break;
            case 1048576:  weight = (const float*)d_in[i]; break;
            case 1024:     bias   = (const float*)d_in[i]; break;
            case 64:       scale  = (const float*)d_in[i]; break;
            case 67108864: wp     = (const float*)d_in[i]; break;
            case 65536:    bp     = (const float*)d_in[i]; break;
            default: break;
        }
    }
    float* out = (float*)d_out;

    cudaFuncSetAttribute(gemm_mma_kernel,
                         cudaFuncAttributeMaxDynamicSharedMemorySize, SMEM_TOTAL);

    reduce_weight_kernel<<<(OUT_F * IN_F) / 4 / 256, 256>>>(weight, scale, wp);
    convert_x_kernel<<<((size_t)MROWS * IN_F) / 8 / 256, 256>>>(x);
    reduce_bias_kernel<<<(OUT_F + 255) / 256, 256>>>(bias, scale, bp);

    dim3 grid(OUT_F / BN, MROWS / BM);   // (4, 128) = 512 CTAs
    gemm_mma_kernel<<<grid, GEMM_THREADS, SMEM_TOTAL>>>(out);
}

// round 8
// speedup vs baseline: 1.1942x; 1.1942x over previous
#include <cuda_runtime.h>
#include <cuda_fp16.h>
#include <cstdint>
#include <cstddef>

#define IN_F   1024
#define OUT_F  1024
#define POP    64
#define MROWS  16384

#define BM 128
#define BN 128
#define BK 64
#define GEMM_THREADS 128
#define NCH (IN_F / BK)            // 16 k-chunks

// smem: fp16 rows of 64 elems (128B) + 16B pad = 144B stride
// (144B = 36 words: ldmatrix 8-row groups and 8-lane cp.async rows both
//  cover all 32 banks conflict-free)
#define ROWB     144
#define A_OFF    0                 // 128 rows x 144B = 18432
#define B_OFF    18432             // 128 rows x 144B = 18432
#define STAGE_SZ 36864
#define NSTAGE   3
#define SMEM_TOTAL (NSTAGE * STAGE_SZ)   // 110592 B -> 2 CTAs/SM

// ---------------- scratch (device globals; allocation is forbidden) --------
__device__ __align__(16) __half g_x[(size_t)MROWS * IN_F];
__device__ __align__(16) __half g_w[(size_t)OUT_F * IN_F];
__device__ float g_beff[OUT_F];

// ---------------- PTX helpers (portable to plain sm_103 target) ------------
__device__ __forceinline__ uint32_t smem_u32(const void* p) {
    uint32_t a;
    asm("{ .reg .u64 t; cvta.to.shared.u64 t, %1; cvt.u32.u64 %0, t; }" : "=r"(a) : "l"(p));
    return a;
}
#define CP16(dst_u32, gptr) \
    asm volatile("cp.async.cg.shared.global [%0], [%1], 16;" :: "r"(dst_u32), "l"(gptr) : "memory")
#define CP_COMMIT() asm volatile("cp.async.commit_group;" ::: "memory")
#define CP_WAIT1()  asm volatile("cp.async.wait_group 1;" ::: "memory")
#define CP_WAIT0()  asm volatile("cp.async.wait_group 0;" ::: "memory")

#define LDSM4(r0, r1, r2, r3, addr)                                              \
    asm volatile("ldmatrix.sync.aligned.m8n8.x4.shared.b16 {%0,%1,%2,%3}, [%4];" \
        : "=r"(r0), "=r"(r1), "=r"(r2), "=r"(r3) : "r"(addr))

__device__ __forceinline__ void mma16816(float* d, const uint32_t* a, const uint32_t* b) {
    asm volatile(
        "mma.sync.aligned.m16n8k16.row.col.f32.f16.f16.f32 "
        "{%0,%1,%2,%3}, {%4,%5,%6,%7}, {%8,%9}, {%0,%1,%2,%3};"
        : "+f"(d[0]), "+f"(d[1]), "+f"(d[2]), "+f"(d[3])
        : "r"(a[0]), "r"(a[1]), "r"(a[2]), "r"(a[3]), "r"(b[0]), "r"(b[1]));
}

// ---------------------------------------------------------------------------
// Prep 1: w_eff = weight + sum_i s_i*wp_i (fp32 math), emitted as fp16
// ---------------------------------------------------------------------------
__global__ void reduce_weight_kernel(const float* __restrict__ weight,
                                     const float* __restrict__ scale,
                                     const float* __restrict__ wp) {
    __shared__ float s_scale[POP];
    if (threadIdx.x < POP) s_scale[threadIdx.x] = scale[threadIdx.x];
    __syncthreads();

    size_t base = ((size_t)blockIdx.x * blockDim.x + threadIdx.x) * 4;
    float4 acc = *reinterpret_cast<const float4*>(weight + base);
#pragma unroll 8
    for (int i = 0; i < POP; i++) {
        const float s = s_scale[i];
        float4 p = *reinterpret_cast<const float4*>(wp + (size_t)i * (OUT_F * IN_F) + base);
        acc.x += s * p.x; acc.y += s * p.y; acc.z += s * p.z; acc.w += s * p.w;
    }
    __half h[4] = {__float2half_rn(acc.x), __float2half_rn(acc.y),
                   __float2half_rn(acc.z), __float2half_rn(acc.w)};
    *reinterpret_cast<uint2*>(g_w + base) = *reinterpret_cast<uint2*>(h);
}

// ---------------------------------------------------------------------------
// Prep 2: x -> fp16
// ---------------------------------------------------------------------------
__global__ void convert_x_kernel(const float* __restrict__ x) {
    size_t base = ((size_t)blockIdx.x * blockDim.x + threadIdx.x) * 8;
    float4 a = *reinterpret_cast<const float4*>(x + base);
    float4 b = *reinterpret_cast<const float4*>(x + base + 4);
    __half h[8] = {__float2half_rn(a.x), __float2half_rn(a.y),
                   __float2half_rn(a.z), __float2half_rn(a.w),
                   __float2half_rn(b.x), __float2half_rn(b.y),
                   __float2half_rn(b.z), __float2half_rn(b.w)};
    *reinterpret_cast<uint4*>(g_x + base) = *reinterpret_cast<uint4*>(h);
}

// ---------------------------------------------------------------------------
// Prep 3: bias
// ---------------------------------------------------------------------------
__global__ void reduce_bias_kernel(const float* __restrict__ bias,
                                   const float* __restrict__ scale,
                                   const float* __restrict__ bp) {
    int j = blockIdx.x * blockDim.x + threadIdx.x;
    if (j >= OUT_F) return;
    float acc = bias[j];
#pragma unroll 8
    for (int i = 0; i < POP; i++) acc += scale[i] * bp[i * OUT_F + j];
    g_beff[j] = acc;
}

// ---------------------------------------------------------------------------
// GEMM via mma.sync fp16 single-pass: out = x @ w_eff^T + b_eff (fp32 acc)
// CTA 128x128x64, 128 threads (4 warps, 2x2), warp tile 64x64.
// 3-stage cp.async pipeline, 108KB smem -> 2 independent CTAs per SM
// (barrier bubbles of one CTA overlap with the other's MMA stream).
// ---------------------------------------------------------------------------
__global__ __launch_bounds__(GEMM_THREADS, 2)
void gemm_mma_kernel(float* __restrict__ out) {
    extern __shared__ char smem[];
    const uint32_t sb = smem_u32(smem);
    const int tid  = threadIdx.x;
    const int wid  = tid >> 5;
    const int lane = tid & 31;
    const int wm   = wid & 1;          // 2 m-warps (64 rows each)
    const int wn   = wid >> 1;         // 2 n-warps (64 cols each)
    const int m0   = blockIdx.y * BM;
    const int n0   = blockIdx.x * BN;

    float acc[4][8][4];
#pragma unroll
    for (int a = 0; a < 4; a++)
#pragma unroll
        for (int b = 0; b < 8; b++)
#pragma unroll
            for (int c = 0; c < 4; c++) acc[a][b][c] = 0.0f;

    // ---- per-thread ldmatrix base offsets (fragment maps validated R4-R7)
    const int g = lane >> 3, r = lane & 7;
    const uint32_t a_row_off = (uint32_t)((wm * 64 + (g & 1) * 8 + r) * ROWB);
    const uint32_t a_k_off   = (uint32_t)((g >> 1) * 16);
    const uint32_t b_row_off = (uint32_t)((wn * 64 + (g >> 1) * 8 + r) * ROWB);
    const uint32_t b_k_off   = (uint32_t)((g & 1) * 16);

    // ---- stage loader: 16 cp.async x 16B per thread (A: 1024 units, B: 1024)
    auto load_stage = [&](int s, int kt) {
        const uint32_t st = sb + s * STAGE_SZ;
        const int krow = kt * BK;
#pragma unroll
        for (int it = 0; it < 8; it++) {
            int u = tid + it * 128, row = u >> 3, gg = u & 7;
            CP16(st + A_OFF + (uint32_t)(row * ROWB + gg * 16),
                 g_x + (size_t)(m0 + row) * IN_F + krow + gg * 8);
        }
#pragma unroll
        for (int it = 0; it < 8; it++) {
            int u = tid + it * 128, row = u >> 3, gg = u & 7;
            CP16(st + B_OFF + (uint32_t)(row * ROWB + gg * 16),
                 g_w + (size_t)(n0 + row) * IN_F + krow + gg * 8);
        }
        CP_COMMIT();
    };

    // ---- pipeline prologue: 2 stages in flight
    load_stage(0, 0);
    load_stage(1, 1);

    for (int c = 0; c < NCH; c++) {
        if (c < NCH - 1) { CP_WAIT1(); } else { CP_WAIT0(); }
        __syncthreads();                       // chunk c resident
        if (c + 2 < NCH) load_stage((c + 2) % NSTAGE, c + 2);

        const uint32_t st = sb + (c % NSTAGE) * STAGE_SZ;
#pragma unroll
        for (int ks = 0; ks < 4; ks++) {       // 4 k-steps of 16 inside BK=64
            uint32_t ah[4][4];
#pragma unroll
            for (int mt = 0; mt < 4; mt++) {
                uint32_t aaddr = st + A_OFF + a_row_off + (uint32_t)(mt * 16 * ROWB)
                               + a_k_off + (uint32_t)(ks * 32);
                LDSM4(ah[mt][0], ah[mt][1], ah[mt][2], ah[mt][3], aaddr);
            }
#pragma unroll
            for (int np = 0; np < 4; np++) {
                uint32_t bh[4];
                uint32_t baddr = st + B_OFF + b_row_off + (uint32_t)(np * 16 * ROWB)
                               + b_k_off + (uint32_t)(ks * 32);
                LDSM4(bh[0], bh[1], bh[2], bh[3], baddr);
#pragma unroll
                for (int mt = 0; mt < 4; mt++) {
                    mma16816(acc[mt][2 * np],     ah[mt], bh);
                    mma16816(acc[mt][2 * np + 1], ah[mt], bh + 2);
                }
            }
        }
        __syncthreads();                       // done reading stage c
    }

    // ---- epilogue: c-frag m16n8 layout: rows lane/4 & +8, cols 2*(lane%4)
    const int erow = lane >> 2;
    const int ecol = 2 * (lane & 3);
#pragma unroll
    for (int mt = 0; mt < 4; mt++) {
        const int mrow = m0 + wm * 64 + mt * 16 + erow;
#pragma unroll
        for (int j = 0; j < 8; j++) {
            const int col = n0 + wn * 64 + j * 8 + ecol;
            const float b0 = g_beff[col], b1 = g_beff[col + 1];
            float2 v0 = make_float2(acc[mt][j][0] + b0, acc[mt][j][1] + b1);
            float2 v1 = make_float2(acc[mt][j][2] + b0, acc[mt][j][3] + b1);
            *reinterpret_cast<float2*>(out + (size_t)mrow * OUT_F + col)       = v0;
            *reinterpret_cast<float2*>(out + (size_t)(mrow + 8) * OUT_F + col) = v1;
        }
    }
}

// ---------------------------------------------------------------------------
// Launch. Inputs identified BY ELEMENT COUNT (all unique, order-independent).
// fp16 inputs arrive as fp32 on device (confirmed R3).
// ---------------------------------------------------------------------------
extern "C" void kernel_launch(void* const* d_in, const int* in_sizes, int n_in,
                              void* d_out, int out_size) {
    const float *x = nullptr, *weight = nullptr, *bias = nullptr,
                *scale = nullptr, *wp = nullptr, *bp = nullptr;
    for (int i = 0; i < n_in; i++) {
        switch (in_sizes[i]) {
            case 16777216: x      = (const float*)d_in[i]; break;
            case 1048576:  weight = (const float*)d_in[i]; break;
            case 1024:     bias   = (const float*)d_in[i]; break;
            case 64:       scale  = (const float*)d_in[i]; break;
            case 67108864: wp     = (const float*)d_in[i]; break;
            case 65536:    bp     = (const float*)d_in[i]; break;
            default: break;
        }
    }
    float* out = (float*)d_out;

    cudaFuncSetAttribute(gemm_mma_kernel,
                         cudaFuncAttributeMaxDynamicSharedMemorySize, SMEM_TOTAL);

    reduce_weight_kernel<<<(OUT_F * IN_F) / 4 / 256, 256>>>(weight, scale, wp);
    convert_x_kernel<<<((size_t)MROWS * IN_F) / 8 / 256, 256>>>(x);
    reduce_bias_kernel<<<(OUT_F + 255) / 256, 256>>>(bias, scale, bp);

    dim3 grid(OUT_F / BN, MROWS / BM);   // (8, 128) = 1024 CTAs
    gemm_mma_kernel<<<grid, GEMM_THREADS, SMEM_TOTAL>>>(out);
}

// round 9
// speedup vs baseline: 1.2213x; 1.0227x over previous
#include <cuda_runtime.h>
#include <cuda_fp16.h>
#include <cstdint>
#include <cstddef>

#define IN_F   1024
#define OUT_F  1024
#define POP    64
#define MROWS  16384

#define BM 128
#define BN 128
#define BK 64
#define GEMM_THREADS 128
#define NCH (IN_F / BK)            // 16 k-chunks

// smem: fp16 rows of 64 elems (128B) + 16B pad = 144B stride
#define ROWB     144
#define A_OFF    0                 // 128 rows x 144B = 18432
#define B_OFF    18432
#define STAGE_SZ 36864
#define NSTAGE   3
#define SMEM_TOTAL (NSTAGE * STAGE_SZ)   // 110592 B -> 2 CTAs/SM

// ---------------- scratch (device globals; allocation is forbidden) --------
__device__ __align__(16) __half g_x[(size_t)MROWS * IN_F];
__device__ __align__(16) __half g_w[(size_t)OUT_F * IN_F];
__device__ float g_beff[OUT_F];

// ---------------- PTX helpers (portable to plain sm_103 target) ------------
__device__ __forceinline__ uint32_t smem_u32(const void* p) {
    uint32_t a;
    asm("{ .reg .u64 t; cvta.to.shared.u64 t, %1; cvt.u32.u64 %0, t; }" : "=r"(a) : "l"(p));
    return a;
}
#define CP16(dst_u32, gptr) \
    asm volatile("cp.async.cg.shared.global [%0], [%1], 16;" :: "r"(dst_u32), "l"(gptr) : "memory")
#define CP_COMMIT() asm volatile("cp.async.commit_group;" ::: "memory")
#define CP_WAIT1()  asm volatile("cp.async.wait_group 1;" ::: "memory")
#define CP_WAIT0()  asm volatile("cp.async.wait_group 0;" ::: "memory")

#define LDSM4(r0, r1, r2, r3, addr)                                              \
    asm volatile("ldmatrix.sync.aligned.m8n8.x4.shared.b16 {%0,%1,%2,%3}, [%4];" \
        : "=r"(r0), "=r"(r1), "=r"(r2), "=r"(r3) : "r"(addr))

__device__ __forceinline__ void mma16816(float* d, const uint32_t* a, const uint32_t* b) {
    asm volatile(
        "mma.sync.aligned.m16n8k16.row.col.f32.f16.f16.f32 "
        "{%0,%1,%2,%3}, {%4,%5,%6,%7}, {%8,%9}, {%0,%1,%2,%3};"
        : "+f"(d[0]), "+f"(d[1]), "+f"(d[2]), "+f"(d[3])
        : "r"(a[0]), "r"(a[1]), "r"(a[2]), "r"(a[3]), "r"(b[0]), "r"(b[1]));
}

// ---------------------------------------------------------------------------
// Fused prep: blocks [0,1024) weight-reduce, [1024,9216) x->fp16, [9216,9220) bias.
// Overlaps the two independent DRAM streams in one launch.
// ---------------------------------------------------------------------------
#define WBLK 1024
#define XBLK 8192
__global__ void prep_kernel(const float* __restrict__ weight,
                            const float* __restrict__ scale,
                            const float* __restrict__ wp,
                            const float* __restrict__ x,
                            const float* __restrict__ bias,
                            const float* __restrict__ bp) {
    const int b = blockIdx.x;
    if (b < WBLK) {
        // ---- w_eff = weight + sum_i s_i*wp_i (fp32 math), emitted as fp16
        __shared__ float s_scale[POP];
        if (threadIdx.x < POP) s_scale[threadIdx.x] = scale[threadIdx.x];
        __syncthreads();
        size_t base = ((size_t)b * blockDim.x + threadIdx.x) * 4;
        float4 acc = *reinterpret_cast<const float4*>(weight + base);
#pragma unroll 8
        for (int i = 0; i < POP; i++) {
            const float s = s_scale[i];
            float4 p = *reinterpret_cast<const float4*>(wp + (size_t)i * (OUT_F * IN_F) + base);
            acc.x += s * p.x; acc.y += s * p.y; acc.z += s * p.z; acc.w += s * p.w;
        }
        __half h[4] = {__float2half_rn(acc.x), __float2half_rn(acc.y),
                       __float2half_rn(acc.z), __float2half_rn(acc.w)};
        *reinterpret_cast<uint2*>(g_w + base) = *reinterpret_cast<uint2*>(h);
    } else if (b < WBLK + XBLK) {
        // ---- x -> fp16
        size_t base = ((size_t)(b - WBLK) * blockDim.x + threadIdx.x) * 8;
        float4 a = *reinterpret_cast<const float4*>(x + base);
        float4 bb = *reinterpret_cast<const float4*>(x + base + 4);
        __half h[8] = {__float2half_rn(a.x),  __float2half_rn(a.y),
                       __float2half_rn(a.z),  __float2half_rn(a.w),
                       __float2half_rn(bb.x), __float2half_rn(bb.y),
                       __float2half_rn(bb.z), __float2half_rn(bb.w)};
        *reinterpret_cast<uint4*>(g_x + base) = *reinterpret_cast<uint4*>(h);
    } else {
        // ---- bias reduce
        int j = (b - WBLK - XBLK) * blockDim.x + threadIdx.x;
        if (j < OUT_F) {
            float acc = bias[j];
#pragma unroll 8
            for (int i = 0; i < POP; i++) acc += scale[i] * bp[i * OUT_F + j];
            g_beff[j] = acc;
        }
    }
}

// ---------------------------------------------------------------------------
// GEMM via mma.sync fp16 single-pass: out = x @ w_eff^T + b_eff (fp32 acc)
// CTA 128x128x64, 128 threads (4 warps, 2x2), warp tile 64x64, 3-stage
// cp.async pipeline, 2 CTAs/SM, ONE barrier per chunk, double-buffered
// ldmatrix fragments (prefetch ks+1 during ks MMAs).
// ---------------------------------------------------------------------------
__global__ __launch_bounds__(GEMM_THREADS, 2)
void gemm_mma_kernel(float* __restrict__ out) {
    extern __shared__ char smem[];
    const uint32_t sb = smem_u32(smem);
    const int tid  = threadIdx.x;
    const int wid  = tid >> 5;
    const int lane = tid & 31;
    const int wm   = wid & 1;
    const int wn   = wid >> 1;
    const int m0   = blockIdx.y * BM;
    const int n0   = blockIdx.x * BN;

    float acc[4][8][4];
#pragma unroll
    for (int a = 0; a < 4; a++)
#pragma unroll
        for (int b = 0; b < 8; b++)
#pragma unroll
            for (int c = 0; c < 4; c++) acc[a][b][c] = 0.0f;

    const int g = lane >> 3, r = lane & 7;
    const uint32_t a_row_off = (uint32_t)((wm * 64 + (g & 1) * 8 + r) * ROWB);
    const uint32_t a_k_off   = (uint32_t)((g >> 1) * 16);
    const uint32_t b_row_off = (uint32_t)((wn * 64 + (g >> 1) * 8 + r) * ROWB);
    const uint32_t b_k_off   = (uint32_t)((g & 1) * 16);

    auto load_stage = [&](int s, int kt) {
        const uint32_t st = sb + s * STAGE_SZ;
        const int krow = kt * BK;
#pragma unroll
        for (int it = 0; it < 8; it++) {
            int u = tid + it * 128, row = u >> 3, gg = u & 7;
            CP16(st + A_OFF + (uint32_t)(row * ROWB + gg * 16),
                 g_x + (size_t)(m0 + row) * IN_F + krow + gg * 8);
        }
#pragma unroll
        for (int it = 0; it < 8; it++) {
            int u = tid + it * 128, row = u >> 3, gg = u & 7;
            CP16(st + B_OFF + (uint32_t)(row * ROWB + gg * 16),
                 g_w + (size_t)(n0 + row) * IN_F + krow + gg * 8);
        }
        CP_COMMIT();
    };

    load_stage(0, 0);
    load_stage(1, 1);

    for (int c = 0; c < NCH; c++) {
        if (c < NCH - 1) { CP_WAIT1(); } else { CP_WAIT0(); }
        __syncthreads();                       // chunk c resident (single barrier)
        if (c + 2 < NCH) load_stage((c + 2) % NSTAGE, c + 2);

        const uint32_t st = sb + (c % NSTAGE) * STAGE_SZ;
        const uint32_t abase = st + A_OFF + a_row_off + a_k_off;
        const uint32_t bbase = st + B_OFF + b_row_off + b_k_off;

        uint32_t ah[2][4][4], bh[2][4][4];
        // prime ks=0 fragments
#pragma unroll
        for (int mt = 0; mt < 4; mt++)
            LDSM4(ah[0][mt][0], ah[0][mt][1], ah[0][mt][2], ah[0][mt][3],
                  abase + (uint32_t)(mt * 16 * ROWB));
#pragma unroll
        for (int np = 0; np < 4; np++)
            LDSM4(bh[0][np][0], bh[0][np][1], bh[0][np][2], bh[0][np][3],
                  bbase + (uint32_t)(np * 16 * ROWB));

#pragma unroll
        for (int ks = 0; ks < 4; ks++) {
            const int cur = ks & 1, nxt = cur ^ 1;
            if (ks < 3) {                      // prefetch ks+1 while ks MMAs run
                const uint32_t ko = (uint32_t)((ks + 1) * 32);
#pragma unroll
                for (int mt = 0; mt < 4; mt++)
                    LDSM4(ah[nxt][mt][0], ah[nxt][mt][1], ah[nxt][mt][2], ah[nxt][mt][3],
                          abase + (uint32_t)(mt * 16 * ROWB) + ko);
#pragma unroll
                for (int np = 0; np < 4; np++)
                    LDSM4(bh[nxt][np][0], bh[nxt][np][1], bh[nxt][np][2], bh[nxt][np][3],
                          bbase + (uint32_t)(np * 16 * ROWB) + ko);
            }
#pragma unroll
            for (int np = 0; np < 4; np++)
#pragma unroll
                for (int mt = 0; mt < 4; mt++) {
                    mma16816(acc[mt][2 * np],     ah[cur][mt], bh[cur][np]);
                    mma16816(acc[mt][2 * np + 1], ah[cur][mt], bh[cur][np] + 2);
                }
        }
    }

    // ---- epilogue: c-frag m16n8 layout: rows lane/4 & +8, cols 2*(lane%4)
    const int erow = lane >> 2;
    const int ecol = 2 * (lane & 3);
#pragma unroll
    for (int mt = 0; mt < 4; mt++) {
        const int mrow = m0 + wm * 64 + mt * 16 + erow;
#pragma unroll
        for (int j = 0; j < 8; j++) {
            const int col = n0 + wn * 64 + j * 8 + ecol;
            const float b0 = g_beff[col], b1 = g_beff[col + 1];
            float2 v0 = make_float2(acc[mt][j][0] + b0, acc[mt][j][1] + b1);
            float2 v1 = make_float2(acc[mt][j][2] + b0, acc[mt][j][3] + b1);
            *reinterpret_cast<float2*>(out + (size_t)mrow * OUT_F + col)       = v0;
            *reinterpret_cast<float2*>(out + (size_t)(mrow + 8) * OUT_F + col) = v1;
        }
    }
}

// ---------------------------------------------------------------------------
// Launch. Inputs identified BY ELEMENT COUNT (all unique, order-independent).
// fp16 inputs arrive as fp32 on device (confirmed R3).
// ---------------------------------------------------------------------------
extern "C" void kernel_launch(void* const* d_in, const int* in_sizes, int n_in,
                              void* d_out, int out_size) {
    const float *x = nullptr, *weight = nullptr, *bias = nullptr,
                *scale = nullptr, *wp = nullptr, *bp = nullptr;
    for (int i = 0; i < n_in; i++) {
        switch (in_sizes[i]) {
            case 16777216: x      = (const float*)d_in[i]; break;
            case 1048576:  weight = (const float*)d_in[i]; break;
            case 1024:     bias   = (const float*)d_in[i]; break;
            case 64:       scale  = (const float*)d_in[i]; break;
            case 67108864: wp     = (const float*)d_in[i]; break;
            case 65536:    bp     = (const float*)d_in[i]; break;
            default: break;
        }
    }
    float* out = (float*)d_out;

    cudaFuncSetAttribute(gemm_mma_kernel,
                         cudaFuncAttributeMaxDynamicSharedMemorySize, SMEM_TOTAL);

    prep_kernel<<<WBLK + XBLK + 4, 256>>>(weight, scale, wp, x, bias, bp);

    dim3 grid(OUT_F / BN, MROWS / BM);   // (8, 128) = 1024 CTAs
    gemm_mma_kernel<<<grid, GEMM_THREADS, SMEM_TOTAL>>>(out);
}

// round 10
// speedup vs baseline: 1.2992x; 1.0638x over previous
#include <cuda_runtime.h>
#include <cuda_fp16.h>
#include <cstdint>
#include <cstddef>

#define IN_F   1024
#define OUT_F  1024
#define POP    64
#define MROWS  16384

#define BM 128
#define BN 128
#define BK 64
#define GEMM_THREADS 128
#define NCH (IN_F / BK)            // 16 k-chunks

// smem: fp16 rows of 64 elems (128B) + 16B pad = 144B stride (conflict-free)
#define ROWB     144
#define A_OFF    0                 // 128 rows x 144B = 18432
#define B_OFF    18432
#define STAGE_SZ 36864
#define NSTAGE   2
#define SMEM_TOTAL (NSTAGE * STAGE_SZ)   // 73728 B -> 3 CTAs/SM (216KB of 228KB)

// ---------------- scratch (device globals; allocation is forbidden) --------
__device__ __align__(16) __half g_x[(size_t)MROWS * IN_F];
__device__ __align__(16) __half g_w[(size_t)OUT_F * IN_F];
__device__ float g_beff[OUT_F];

// ---------------- PTX helpers (portable to plain sm_103 target) ------------
__device__ __forceinline__ uint32_t smem_u32(const void* p) {
    uint32_t a;
    asm("{ .reg .u64 t; cvta.to.shared.u64 t, %1; cvt.u32.u64 %0, t; }" : "=r"(a) : "l"(p));
    return a;
}
#define CP16(dst_u32, gptr) \
    asm volatile("cp.async.cg.shared.global [%0], [%1], 16;" :: "r"(dst_u32), "l"(gptr) : "memory")
#define CP_COMMIT() asm volatile("cp.async.commit_group;" ::: "memory")
#define CP_WAIT1()  asm volatile("cp.async.wait_group 1;" ::: "memory")
#define CP_WAIT0()  asm volatile("cp.async.wait_group 0;" ::: "memory")

#define LDSM4(r0, r1, r2, r3, addr)                                              \
    asm volatile("ldmatrix.sync.aligned.m8n8.x4.shared.b16 {%0,%1,%2,%3}, [%4];" \
        : "=r"(r0), "=r"(r1), "=r"(r2), "=r"(r3) : "r"(addr))

__device__ __forceinline__ void mma16816(float* d, const uint32_t* a, const uint32_t* b) {
    asm volatile(
        "mma.sync.aligned.m16n8k16.row.col.f32.f16.f16.f32 "
        "{%0,%1,%2,%3}, {%4,%5,%6,%7}, {%8,%9}, {%0,%1,%2,%3};"
        : "+f"(d[0]), "+f"(d[1]), "+f"(d[2]), "+f"(d[3])
        : "r"(a[0]), "r"(a[1]), "r"(a[2]), "r"(a[3]), "r"(b[0]), "r"(b[1]));
}

// ---------------------------------------------------------------------------
// Fused prep: blocks [0,1024) weight-reduce, [1024,9216) x->fp16, [9216,9220) bias.
// ---------------------------------------------------------------------------
#define WBLK 1024
#define XBLK 8192
__global__ void prep_kernel(const float* __restrict__ weight,
                            const float* __restrict__ scale,
                            const float* __restrict__ wp,
                            const float* __restrict__ x,
                            const float* __restrict__ bias,
                            const float* __restrict__ bp) {
    const int b = blockIdx.x;
    if (b < WBLK) {
        __shared__ float s_scale[POP];
        if (threadIdx.x < POP) s_scale[threadIdx.x] = scale[threadIdx.x];
        __syncthreads();
        size_t base = ((size_t)b * blockDim.x + threadIdx.x) * 4;
        float4 acc = *reinterpret_cast<const float4*>(weight + base);
#pragma unroll 8
        for (int i = 0; i < POP; i++) {
            const float s = s_scale[i];
            float4 p = *reinterpret_cast<const float4*>(wp + (size_t)i * (OUT_F * IN_F) + base);
            acc.x += s * p.x; acc.y += s * p.y; acc.z += s * p.z; acc.w += s * p.w;
        }
        __half h[4] = {__float2half_rn(acc.x), __float2half_rn(acc.y),
                       __float2half_rn(acc.z), __float2half_rn(acc.w)};
        *reinterpret_cast<uint2*>(g_w + base) = *reinterpret_cast<uint2*>(h);
    } else if (b < WBLK + XBLK) {
        size_t base = ((size_t)(b - WBLK) * blockDim.x + threadIdx.x) * 8;
        float4 a = *reinterpret_cast<const float4*>(x + base);
        float4 bb = *reinterpret_cast<const float4*>(x + base + 4);
        __half h[8] = {__float2half_rn(a.x),  __float2half_rn(a.y),
                       __float2half_rn(a.z),  __float2half_rn(a.w),
                       __float2half_rn(bb.x), __float2half_rn(bb.y),
                       __float2half_rn(bb.z), __float2half_rn(bb.w)};
        *reinterpret_cast<uint4*>(g_x + base) = *reinterpret_cast<uint4*>(h);
    } else {
        int j = (b - WBLK - XBLK) * blockDim.x + threadIdx.x;
        if (j < OUT_F) {
            float acc = bias[j];
#pragma unroll 8
            for (int i = 0; i < POP; i++) acc += scale[i] * bp[i * OUT_F + j];
            g_beff[j] = acc;
        }
    }
}

// ---------------------------------------------------------------------------
// GEMM via mma.sync fp16 single-pass: out = x @ w_eff^T + b_eff (fp32 acc)
// CTA 128x128x64, 128 threads (4 warps, 2x2), warp tile 64x64, 2-stage
// cp.async pipeline, 3 CTAs/SM (3 independent HMMA streams per SMSP),
// one barrier per chunk.
// ---------------------------------------------------------------------------
__global__ __launch_bounds__(GEMM_THREADS, 3)
void gemm_mma_kernel(float* __restrict__ out) {
    extern __shared__ char smem[];
    const uint32_t sb = smem_u32(smem);
    const int tid  = threadIdx.x;
    const int wid  = tid >> 5;
    const int lane = tid & 31;
    const int wm   = wid & 1;
    const int wn   = wid >> 1;
    const int m0   = blockIdx.y * BM;
    const int n0   = blockIdx.x * BN;

    float acc[4][8][4];
#pragma unroll
    for (int a = 0; a < 4; a++)
#pragma unroll
        for (int b = 0; b < 8; b++)
#pragma unroll
            for (int c = 0; c < 4; c++) acc[a][b][c] = 0.0f;

    const int g = lane >> 3, r = lane & 7;
    const uint32_t a_row_off = (uint32_t)((wm * 64 + (g & 1) * 8 + r) * ROWB);
    const uint32_t a_k_off   = (uint32_t)((g >> 1) * 16);
    const uint32_t b_row_off = (uint32_t)((wn * 64 + (g >> 1) * 8 + r) * ROWB);
    const uint32_t b_k_off   = (uint32_t)((g & 1) * 16);

    auto load_stage = [&](int s, int kt) {
        const uint32_t st = sb + s * STAGE_SZ;
        const int krow = kt * BK;
#pragma unroll
        for (int it = 0; it < 8; it++) {
            int u = tid + it * 128, row = u >> 3, gg = u & 7;
            CP16(st + A_OFF + (uint32_t)(row * ROWB + gg * 16),
                 g_x + (size_t)(m0 + row) * IN_F + krow + gg * 8);
        }
#pragma unroll
        for (int it = 0; it < 8; it++) {
            int u = tid + it * 128, row = u >> 3, gg = u & 7;
            CP16(st + B_OFF + (uint32_t)(row * ROWB + gg * 16),
                 g_w + (size_t)(n0 + row) * IN_F + krow + gg * 8);
        }
        CP_COMMIT();
    };

    load_stage(0, 0);

    for (int c = 0; c < NCH; c++) {
        // Barrier first: guarantees chunk c-1's readers are done before we
        // overwrite buffer (c+1)&1 == (c-1)&1 with the next prefetch.
        __syncthreads();
        if (c + 1 < NCH) {
            load_stage((c + 1) & 1, c + 1);
            CP_WAIT1();                        // chunk c resident; c+1 in flight
        } else {
            CP_WAIT0();
        }
        __syncthreads();                       // all warps see stage c complete

        const uint32_t st = sb + (c & 1) * STAGE_SZ;
#pragma unroll
        for (int ks = 0; ks < 4; ks++) {
            uint32_t ah[4][4];
#pragma unroll
            for (int mt = 0; mt < 4; mt++) {
                uint32_t aaddr = st + A_OFF + a_row_off + (uint32_t)(mt * 16 * ROWB)
                               + a_k_off + (uint32_t)(ks * 32);
                LDSM4(ah[mt][0], ah[mt][1], ah[mt][2], ah[mt][3], aaddr);
            }
#pragma unroll
            for (int np = 0; np < 4; np++) {
                uint32_t bh[4];
                uint32_t baddr = st + B_OFF + b_row_off + (uint32_t)(np * 16 * ROWB)
                               + b_k_off + (uint32_t)(ks * 32);
                LDSM4(bh[0], bh[1], bh[2], bh[3], baddr);
#pragma unroll
                for (int mt = 0; mt < 4; mt++) {
                    mma16816(acc[mt][2 * np],     ah[mt], bh);
                    mma16816(acc[mt][2 * np + 1], ah[mt], bh + 2);
                }
            }
        }
    }

    // ---- epilogue: c-frag m16n8 layout: rows lane/4 & +8, cols 2*(lane%4)
    const int erow = lane >> 2;
    const int ecol = 2 * (lane & 3);
#pragma unroll
    for (int mt = 0; mt < 4; mt++) {
        const int mrow = m0 + wm * 64 + mt * 16 + erow;
#pragma unroll
        for (int j = 0; j < 8; j++) {
            const int col = n0 + wn * 64 + j * 8 + ecol;
            const float b0 = g_beff[col], b1 = g_beff[col + 1];
            float2 v0 = make_float2(acc[mt][j][0] + b0, acc[mt][j][1] + b1);
            float2 v1 = make_float2(acc[mt][j][2] + b0, acc[mt][j][3] + b1);
            *reinterpret_cast<float2*>(out + (size_t)mrow * OUT_F + col)       = v0;
            *reinterpret_cast<float2*>(out + (size_t)(mrow + 8) * OUT_F + col) = v1;
        }
    }
}

// ---------------------------------------------------------------------------
// Launch. Inputs identified BY ELEMENT COUNT (all unique, order-independent).
// fp16 inputs arrive as fp32 on device (confirmed R3).
// ---------------------------------------------------------------------------
extern "C" void kernel_launch(void* const* d_in, const int* in_sizes, int n_in,
                              void* d_out, int out_size) {
    const float *x = nullptr, *weight = nullptr, *bias = nullptr,
                *scale = nullptr, *wp = nullptr, *bp = nullptr;
    for (int i = 0; i < n_in; i++) {
        switch (in_sizes[i]) {
            case 16777216: x      = (const float*)d_in[i]; break;
            case 1048576:  weight = (const float*)d_in[i]; break;
            case 1024:     bias   = (const float*)d_in[i]; break;
            case 64:       scale  = (const float*)d_in[i]; break;
            case 67108864: wp     = (const float*)d_in[i]; break;
            case 65536:    bp     = (const float*)d_in[i]; break;
            default: break;
        }
    }
    float* out = (float*)d_out;

    cudaFuncSetAttribute(gemm_mma_kernel,
                         cudaFuncAttributeMaxDynamicSharedMemorySize, SMEM_TOTAL);

    prep_kernel<<<WBLK + XBLK + 4, 256>>>(weight, scale, wp, x, bias, bp);

    dim3 grid(OUT_F / BN, MROWS / BM);   // (8, 128) = 1024 CTAs
    gemm_mma_kernel<<<grid, GEMM_THREADS, SMEM_TOTAL>>>(out);
}

// round 12
// speedup vs baseline: 1.3824x; 1.0640x over previous
#include <cuda_runtime.h>
#include <cuda_fp16.h>
#include <cstdint>
#include <cstddef>

#define IN_F   1024
#define OUT_F  1024
#define POP    64
#define MROWS  16384

#define BM 128
#define BN 128
#define BK 64
#define GEMM_THREADS 160           // 4 consumer warps + 1 producer warp
#define NCH (IN_F / BK)            // 16 k-chunks

// smem: fp16 rows of 64 elems (128B) + 16B pad = 144B stride (conflict-free)
#define ROWB     144
#define A_OFF    0                 // 128 rows x 144B = 18432
#define B_OFF    18432
#define STAGE_SZ 36864
#define NSTAGE   3
#define SM_MBAR  0                 // 6 mbarriers (full[3], empty[3]) x 8B
#define SM_TILE0 1024
#define SMEM_TOTAL (SM_TILE0 + NSTAGE * STAGE_SZ)   // 111616 B -> 2 CTAs/SM

// ---------------- scratch (device globals; allocation is forbidden) --------
__device__ __align__(16) __half g_x[(size_t)MROWS * IN_F];
__device__ __align__(16) __half g_w[(size_t)OUT_F * IN_F];
__device__ float g_beff[OUT_F];

// ---------------- PTX helpers (portable to plain sm_103 target) ------------
__device__ __forceinline__ uint32_t smem_u32(const void* p) {
    uint32_t a;
    asm("{ .reg .u64 t; cvta.to.shared.u64 t, %1; cvt.u32.u64 %0, t; }" : "=r"(a) : "l"(p));
    return a;
}
#define CP16(dst_u32, gptr) \
    asm volatile("cp.async.cg.shared.global [%0], [%1], 16;" :: "r"(dst_u32), "l"(gptr) : "memory")
// .noinc is LOAD-BEARING: the default form raises the pending count before the
// async arrive (net-zero vs the phase) and deadlocks a preset-count barrier.
#define CPASYNC_MBAR_ARRIVE_NOINC(a) \
    asm volatile("cp.async.mbarrier.arrive.noinc.shared.b64 [%0];" :: "r"(a) : "memory")
#define MBAR_INIT(a, c) \
    asm volatile("mbarrier.init.shared.b64 [%0], %1;" :: "r"(a), "r"(c) : "memory")
#define MBAR_ARRIVE(a) do { unsigned long long _st;                              \
    asm volatile("mbarrier.arrive.shared.b64 %0, [%1];"                          \
        : "=l"(_st) : "r"(a) : "memory"); (void)_st; } while (0)
#define MBAR_WAIT_PARITY(addr, par) do {                                         \
    uint32_t _m = (addr); uint32_t _p = (par); uint32_t _done;                   \
    asm volatile("{\n\t.reg .pred p;\n\t"                                        \
        "mbarrier.try_wait.parity.acquire.cta.shared::cta.b64 p, [%1], %2;\n\t"  \
        "selp.b32 %0, 1, 0, p;\n\t}" : "=r"(_done) : "r"(_m), "r"(_p) : "memory"); \
    if (!_done) {                                                                \
        asm volatile("{\n\t.reg .pred P1;\n\tWL_%=: \n\t"                        \
            "mbarrier.try_wait.parity.acquire.cta.shared::cta.b64 P1, [%0], %1, 0x989680;\n\t" \
            "@P1 bra.uni WD_%=;\n\tbra.uni WL_%=;\n\tWD_%=:\n\t}"                \
            :: "r"(_m), "r"(_p) : "memory");                                     \
    } } while (0)

#define LDSM4(r0, r1, r2, r3, addr)                                              \
    asm volatile("ldmatrix.sync.aligned.m8n8.x4.shared.b16 {%0,%1,%2,%3}, [%4];" \
        : "=r"(r0), "=r"(r1), "=r"(r2), "=r"(r3) : "r"(addr))

__device__ __forceinline__ void mma16816(float* d, const uint32_t* a, const uint32_t* b) {
    asm volatile(
        "mma.sync.aligned.m16n8k16.row.col.f32.f16.f16.f32 "
        "{%0,%1,%2,%3}, {%4,%5,%6,%7}, {%8,%9}, {%0,%1,%2,%3};"
        : "+f"(d[0]), "+f"(d[1]), "+f"(d[2]), "+f"(d[3])
        : "r"(a[0]), "r"(a[1]), "r"(a[2]), "r"(a[3]), "r"(b[0]), "r"(b[1]));
}

// ---------------------------------------------------------------------------
// Fused prep: blocks [0,1024) weight-reduce, [1024,9216) x->fp16, [9216,9220) bias.
// ---------------------------------------------------------------------------
#define WBLK 1024
#define XBLK 8192
__global__ void prep_kernel(const float* __restrict__ weight,
                            const float* __restrict__ scale,
                            const float* __restrict__ wp,
                            const float* __restrict__ x,
                            const float* __restrict__ bias,
                            const float* __restrict__ bp) {
    const int b = blockIdx.x;
    if (b < WBLK) {
        __shared__ float s_scale[POP];
        if (threadIdx.x < POP) s_scale[threadIdx.x] = scale[threadIdx.x];
        __syncthreads();
        size_t base = ((size_t)b * blockDim.x + threadIdx.x) * 4;
        float4 acc = *reinterpret_cast<const float4*>(weight + base);
#pragma unroll 8
        for (int i = 0; i < POP; i++) {
            const float s = s_scale[i];
            float4 p = *reinterpret_cast<const float4*>(wp + (size_t)i * (OUT_F * IN_F) + base);
            acc.x += s * p.x; acc.y += s * p.y; acc.z += s * p.z; acc.w += s * p.w;
        }
        __half h[4] = {__float2half_rn(acc.x), __float2half_rn(acc.y),
                       __float2half_rn(acc.z), __float2half_rn(acc.w)};
        *reinterpret_cast<uint2*>(g_w + base) = *reinterpret_cast<uint2*>(h);
    } else if (b < WBLK + XBLK) {
        size_t base = ((size_t)(b - WBLK) * blockDim.x + threadIdx.x) * 8;
        float4 a = *reinterpret_cast<const float4*>(x + base);
        float4 bb = *reinterpret_cast<const float4*>(x + base + 4);
        __half h[8] = {__float2half_rn(a.x),  __float2half_rn(a.y),
                       __float2half_rn(a.z),  __float2half_rn(a.w),
                       __float2half_rn(bb.x), __float2half_rn(bb.y),
                       __float2half_rn(bb.z), __float2half_rn(bb.w)};
        *reinterpret_cast<uint4*>(g_x + base) = *reinterpret_cast<uint4*>(h);
    } else {
        int j = (b - WBLK - XBLK) * blockDim.x + threadIdx.x;
        if (j < OUT_F) {
            float acc = bias[j];
#pragma unroll 8
            for (int i = 0; i < POP; i++) acc += scale[i] * bp[i * OUT_F + j];
            g_beff[j] = acc;
        }
    }
}

// ---------------------------------------------------------------------------
// GEMM via mma.sync fp16 single-pass, warp-specialized:
//   warp 4  = producer (cp.async + cp.async.mbarrier.arrive.noinc on full[s])
//   warps 0-3 = consumers (64x64 tiles), free-running on full/empty parity,
//               NO __syncthreads in the mainloop.
// CTA 128x128x64, 3-stage ring, 2 CTAs/SM.
//   full[s]:  count 32  (producer lanes' async .noinc arrives)
//   empty[s]: count 128 (consumer lanes arrive after reading)
// Chunk kt -> stage s=kt%3, use u=kt/3.
//   consumer waits full[s] parity u&1; producer (u>0) waits empty[s] parity (u-1)&1.
// ---------------------------------------------------------------------------
__global__ __launch_bounds__(GEMM_THREADS, 2)
void gemm_mma_kernel(float* __restrict__ out) {
    extern __shared__ char smem[];
    const uint32_t sb = smem_u32(smem);
    const int tid  = threadIdx.x;
    const int wid  = tid >> 5;
    const int lane = tid & 31;
    const int m0   = blockIdx.y * BM;
    const int n0   = blockIdx.x * BN;

    const uint32_t mb_full  = sb + SM_MBAR;        // full[s]  = mb_full + 8s
    const uint32_t mb_empty = sb + SM_MBAR + 24;   // empty[s] = mb_empty + 8s

    if (tid == 0) {
#pragma unroll
        for (int s = 0; s < NSTAGE; s++) {
            MBAR_INIT(mb_full + 8 * s, 32);
            MBAR_INIT(mb_empty + 8 * s, 128);
        }
    }
    __syncthreads();

    if (wid == 4) {
        // ================= producer =================
        for (int kt = 0; kt < NCH; kt++) {
            const int s = kt % NSTAGE, u = kt / NSTAGE;
            if (u > 0) { MBAR_WAIT_PARITY(mb_empty + 8 * s, (u - 1) & 1); }
            const uint32_t st = sb + SM_TILE0 + s * STAGE_SZ;
            const int krow = kt * BK;
#pragma unroll
            for (int it = 0; it < 32; it++) {       // A: 1024 16B units
                int uu = it * 32 + lane, row = uu >> 3, gg = uu & 7;
                CP16(st + A_OFF + (uint32_t)(row * ROWB + gg * 16),
                     g_x + (size_t)(m0 + row) * IN_F + krow + gg * 8);
            }
#pragma unroll
            for (int it = 0; it < 32; it++) {       // B: 1024 16B units
                int uu = it * 32 + lane, row = uu >> 3, gg = uu & 7;
                CP16(st + B_OFF + (uint32_t)(row * ROWB + gg * 16),
                     g_w + (size_t)(n0 + row) * IN_F + krow + gg * 8);
            }
            CPASYNC_MBAR_ARRIVE_NOINC(mb_full + 8 * s);  // fires when lane's copies land
        }
        return;
    }

    // ================= consumers (warps 0-3) =================
    const int wm = wid & 1;
    const int wn = wid >> 1;

    float acc[4][8][4];
#pragma unroll
    for (int a = 0; a < 4; a++)
#pragma unroll
        for (int b = 0; b < 8; b++)
#pragma unroll
            for (int c = 0; c < 4; c++) acc[a][b][c] = 0.0f;

    const int g = lane >> 3, r = lane & 7;
    const uint32_t a_row_off = (uint32_t)((wm * 64 + (g & 1) * 8 + r) * ROWB);
    const uint32_t a_k_off   = (uint32_t)((g >> 1) * 16);
    const uint32_t b_row_off = (uint32_t)((wn * 64 + (g >> 1) * 8 + r) * ROWB);
    const uint32_t b_k_off   = (uint32_t)((g & 1) * 16);

    for (int kt = 0; kt < NCH; kt++) {
        const int s = kt % NSTAGE, u = kt / NSTAGE;
        MBAR_WAIT_PARITY(mb_full + 8 * s, u & 1);

        const uint32_t st = sb + SM_TILE0 + s * STAGE_SZ;
#pragma unroll
        for (int ks = 0; ks < 4; ks++) {
            uint32_t ah[4][4];
#pragma unroll
            for (int mt = 0; mt < 4; mt++) {
                uint32_t aaddr = st + A_OFF + a_row_off + (uint32_t)(mt * 16 * ROWB)
                               + a_k_off + (uint32_t)(ks * 32);
                LDSM4(ah[mt][0], ah[mt][1], ah[mt][2], ah[mt][3], aaddr);
            }
#pragma unroll
            for (int np = 0; np < 4; np++) {
                uint32_t bh[4];
                uint32_t baddr = st + B_OFF + b_row_off + (uint32_t)(np * 16 * ROWB)
                               + b_k_off + (uint32_t)(ks * 32);
                LDSM4(bh[0], bh[1], bh[2], bh[3], baddr);
#pragma unroll
                for (int mt = 0; mt < 4; mt++) {
                    mma16816(acc[mt][2 * np],     ah[mt], bh);
                    mma16816(acc[mt][2 * np + 1], ah[mt], bh + 2);
                }
            }
        }
        MBAR_ARRIVE(mb_empty + 8 * s);              // reads done (ldmatrix is sync)
    }

    // ---- epilogue: c-frag m16n8 layout: rows lane/4 & +8, cols 2*(lane%4)
    const int erow = lane >> 2;
    const int ecol = 2 * (lane & 3);
#pragma unroll
    for (int mt = 0; mt < 4; mt++) {
        const int mrow = m0 + wm * 64 + mt * 16 + erow;
#pragma unroll
        for (int j = 0; j < 8; j++) {
            const int col = n0 + wn * 64 + j * 8 + ecol;
            const float b0 = g_beff[col], b1 = g_beff[col + 1];
            float2 v0 = make_float2(acc[mt][j][0] + b0, acc[mt][j][1] + b1);
            float2 v1 = make_float2(acc[mt][j][2] + b0, acc[mt][j][3] + b1);
            *reinterpret_cast<float2*>(out + (size_t)mrow * OUT_F + col)       = v0;
            *reinterpret_cast<float2*>(out + (size_t)(mrow + 8) * OUT_F + col) = v1;
        }
    }
}

// ---------------------------------------------------------------------------
// Launch. Inputs identified BY ELEMENT COUNT (all unique, order-independent).
// fp16 inputs arrive as fp32 on device (confirmed R3).
// ---------------------------------------------------------------------------
extern "C" void kernel_launch(void* const* d_in, const int* in_sizes, int n_in,
                              void* d_out, int out_size) {
    const float *x = nullptr, *weight = nullptr, *bias = nullptr,
                *scale = nullptr, *wp = nullptr, *bp = nullptr;
    for (int i = 0; i < n_in; i++) {
        switch (in_sizes[i]) {
            case 16777216: x      = (const float*)d_in[i]; break;
            case 1048576:  weight = (const float*)d_in[i]; break;
            case 1024:     bias   = (const float*)d_in[i]; break;
            case 64:       scale  = (const float*)d_in[i]; break;
            case 67108864: wp     = (const float*)d_in[i]; break;
            case 65536:    bp     = (const float*)d_in[i]; break;
            default: break;
        }
    }
    float* out = (float*)d_out;

    cudaFuncSetAttribute(gemm_mma_kernel,
                         cudaFuncAttributeMaxDynamicSharedMemorySize, SMEM_TOTAL);

    prep_kernel<<<WBLK + XBLK + 4, 256>>>(weight, scale, wp, x, bias, bp);

    dim3 grid(OUT_F / BN, MROWS / BM);   // (8, 128) = 1024 CTAs
    gemm_mma_kernel<<<grid, GEMM_THREADS, SMEM_TOTAL>>>(out);
}